// round 1
// baseline (speedup 1.0000x reference)
#include <cuda_runtime.h>
#include <math.h>

#define N_NODES 16384
#define E_EDGES 131072
#define DIM 256
#define HEADS 8
#define HD_ 32
#define INTERM 682

// ---------------- scratch (device globals; no allocation allowed) ----------------
__device__ float g_Q[N_NODES * 768];     // qs / qkv buffer (max 768 wide)
__device__ float g_KV[N_NODES * 512];    // kv buffer
__device__ float g_E[E_EDGES * HEADS];   // per-edge exp(score)
__device__ float g_Dn[N_NODES * HEADS];  // softmax denominators
__device__ float g_AGG[N_NODES * DIM];   // attention aggregate
__device__ float g_X1[N_NODES * DIM];
__device__ float g_X2[N_NODES * DIM];
__device__ float g_T[N_NODES * DIM];
__device__ float g_H[N_NODES * INTERM];
__device__ float g_V[N_NODES * INTERM];

// ---------------- generic fp32 GEMM: C[M,N] = A[M,K] @ B[K,N] ----------------
#define BM 128
#define BN 128
#define BK 16

__global__ __launch_bounds__(256) void gemm_k(const float* __restrict__ A,
                                              const float* __restrict__ B,
                                              float* __restrict__ C,
                                              int M, int K, int N) {
    __shared__ float As[BK][BM + 4];  // +4 pad: breaks 16-way STS bank conflict, keeps 16B align
    __shared__ float Bs[BK][BN];

    int tid = threadIdx.x;
    int tx = tid & 15;
    int ty = tid >> 4;
    int bm = blockIdx.y * BM;
    int bn = blockIdx.x * BN;

    float acc[8][8];
#pragma unroll
    for (int i = 0; i < 8; i++)
#pragma unroll
        for (int j = 0; j < 8; j++) acc[i][j] = 0.f;

    for (int k0 = 0; k0 < K; k0 += BK) {
        // load A tile (BM x BK) into As[k][m]
#pragma unroll
        for (int i = 0; i < 8; i++) {
            int idx = i * 256 + tid;
            int m = idx >> 4;
            int kk = idx & 15;
            int gk = k0 + kk;
            As[kk][m] = (gk < K) ? A[(size_t)(bm + m) * K + gk] : 0.f;
        }
        // load B tile (BK x BN) into Bs[k][n]
#pragma unroll
        for (int i = 0; i < 8; i++) {
            int idx = i * 256 + tid;
            int n = idx & 127;
            int kk = idx >> 7;
            int gk = k0 + kk;
            int gn = bn + n;
            Bs[kk][n] = (gk < K && gn < N) ? B[(size_t)gk * N + gn] : 0.f;
        }
        __syncthreads();

#pragma unroll
        for (int kk = 0; kk < BK; kk++) {
            float4 a0 = *(const float4*)&As[kk][ty * 8];
            float4 a1 = *(const float4*)&As[kk][ty * 8 + 4];
            float4 b0 = *(const float4*)&Bs[kk][tx * 8];
            float4 b1 = *(const float4*)&Bs[kk][tx * 8 + 4];
            float a[8] = {a0.x, a0.y, a0.z, a0.w, a1.x, a1.y, a1.z, a1.w};
            float b[8] = {b0.x, b0.y, b0.z, b0.w, b1.x, b1.y, b1.z, b1.w};
#pragma unroll
            for (int i = 0; i < 8; i++)
#pragma unroll
                for (int j = 0; j < 8; j++) acc[i][j] += a[i] * b[j];
        }
        __syncthreads();
    }

#pragma unroll
    for (int i = 0; i < 8; i++) {
        int m = bm + ty * 8 + i;
        if (m >= M) continue;
#pragma unroll
        for (int j = 0; j < 8; j++) {
            int n = bn + tx * 8 + j;
            if (n < N) C[(size_t)m * N + n] = acc[i][j];
        }
    }
}

// ---------------- edge kernels (one warp per edge) ----------------
// Cross-MHA: Q[N,256] (h*32+d), KV[N,512] layout (h,d,2): k=2d, v=2d+1
__global__ void edge_exp_cross(const float* __restrict__ Q, const float* __restrict__ KV,
                               const int* __restrict__ eidx, float* __restrict__ ew,
                               float* __restrict__ den, float scale) {
    int e = blockIdx.x * 8 + (threadIdx.x >> 5);
    if (e >= E_EDGES) return;
    int lane = threadIdx.x & 31;
    int s = eidx[e];
    int d = eidx[E_EDGES + e];
    const float* qr = Q + (size_t)d * DIM;
    const float* kr = KV + (size_t)s * 512;
#pragma unroll
    for (int h = 0; h < HEADS; h++) {
        float p = qr[h * HD_ + lane] * kr[h * 64 + 2 * lane];
#pragma unroll
        for (int off = 16; off; off >>= 1) p += __shfl_xor_sync(0xffffffffu, p, off);
        float w = expf(p * scale);
        if (lane == 0) {
            ew[(size_t)e * HEADS + h] = w;
            atomicAdd(&den[(size_t)d * HEADS + h], w);
        }
    }
}

__global__ void edge_agg_cross(const float* __restrict__ KV, const int* __restrict__ eidx,
                               const float* __restrict__ ew, const float* __restrict__ den,
                               float* __restrict__ agg) {
    int e = blockIdx.x * 8 + (threadIdx.x >> 5);
    if (e >= E_EDGES) return;
    int lane = threadIdx.x & 31;
    int s = eidx[e];
    int d = eidx[E_EDGES + e];
    const float* kr = KV + (size_t)s * 512;
    float* ar = agg + (size_t)d * DIM;
#pragma unroll
    for (int h = 0; h < HEADS; h++) {
        float w = ew[(size_t)e * HEADS + h] / den[(size_t)d * HEADS + h];
        float v = kr[h * 64 + 2 * lane + 1];
        atomicAdd(&ar[h * HD_ + lane], w * v);
    }
}

// Self-MHA: QKV[N,768] layout (h,d,3): q=3d, k=3d+1, v=3d+2; includes edge_attr, no scale
__global__ void edge_exp_self(const float* __restrict__ QKV, const float* __restrict__ EA,
                              const int* __restrict__ eidx, float* __restrict__ ew,
                              float* __restrict__ den) {
    int e = blockIdx.x * 8 + (threadIdx.x >> 5);
    if (e >= E_EDGES) return;
    int lane = threadIdx.x & 31;
    int s = eidx[e];
    int d = eidx[E_EDGES + e];
    const float* qr = QKV + (size_t)d * 768;
    const float* kr = QKV + (size_t)s * 768;
    const float* ar = EA + (size_t)e * DIM;
#pragma unroll
    for (int h = 0; h < HEADS; h++) {
        float p = qr[h * 96 + 3 * lane] * kr[h * 96 + 3 * lane + 1] * ar[h * HD_ + lane];
#pragma unroll
        for (int off = 16; off; off >>= 1) p += __shfl_xor_sync(0xffffffffu, p, off);
        float w = expf(p);
        if (lane == 0) {
            ew[(size_t)e * HEADS + h] = w;
            atomicAdd(&den[(size_t)d * HEADS + h], w);
        }
    }
}

__global__ void edge_agg_self(const float* __restrict__ QKV, const int* __restrict__ eidx,
                              const float* __restrict__ ew, const float* __restrict__ den,
                              float* __restrict__ agg) {
    int e = blockIdx.x * 8 + (threadIdx.x >> 5);
    if (e >= E_EDGES) return;
    int lane = threadIdx.x & 31;
    int s = eidx[e];
    int d = eidx[E_EDGES + e];
    const float* kr = QKV + (size_t)s * 768;
    float* ar = agg + (size_t)d * DIM;
#pragma unroll
    for (int h = 0; h < HEADS; h++) {
        float w = ew[(size_t)e * HEADS + h] / den[(size_t)d * HEADS + h];
        float v = kr[h * 96 + 3 * lane + 2];
        atomicAdd(&ar[h * HD_ + lane], w * v);
    }
}

// ---------------- fused add + RMS norm (one block per row) ----------------
__global__ void add_rms(const float* __restrict__ A, const float* __restrict__ B,
                        const float* __restrict__ g, float* __restrict__ out) {
    int row = blockIdx.x;
    int t = threadIdx.x;
    float x = A[(size_t)row * DIM + t] + B[(size_t)row * DIM + t];
    float ss = x * x;
#pragma unroll
    for (int off = 16; off; off >>= 1) ss += __shfl_xor_sync(0xffffffffu, ss, off);
    __shared__ float sh[8];
    if ((t & 31) == 0) sh[t >> 5] = ss;
    __syncthreads();
    float tot = sh[0] + sh[1] + sh[2] + sh[3] + sh[4] + sh[5] + sh[6] + sh[7];
    float nrm = sqrtf(tot * (1.0f / DIM));
    out[(size_t)row * DIM + t] = x / fmaxf(nrm, 1e-8f) * g[t];
}

// ---------------- SwiGLU elementwise (in-place on H) ----------------
__global__ void swiglu_k(float* __restrict__ H, const float* __restrict__ V, int total) {
    int i = blockIdx.x * blockDim.x + threadIdx.x;
    if (i < total) {
        float h = H[i];
        H[i] = h / (1.0f + expf(-h)) * V[i];
    }
}

// ---------------- launch ----------------
extern "C" void kernel_launch(void* const* d_in, const int* in_sizes, int n_in,
                              void* d_out, int out_size) {
    const float* root   = (const float*)d_in[0];
    const float* node   = (const float*)d_in[1];
    const float* fringe = (const float*)d_in[2];
    const int* e_ntr = (const int*)d_in[3];
    const int* e_rtr = (const int*)d_in[4];
    const int* e_rtf = (const int*)d_in[5];
    const float* eattr = (const float*)d_in[6];
    const float* ntr_wq  = (const float*)d_in[7];
    const float* ntr_wkv = (const float*)d_in[8];
    const float* ntr_wout= (const float*)d_in[9];
    const float* ntr_g   = (const float*)d_in[10];
    const float* rtr_wqkv= (const float*)d_in[11];
    const float* rtr_wout= (const float*)d_in[12];
    const float* rtr_g   = (const float*)d_in[13];
    const float* ffn_win = (const float*)d_in[14];
    const float* ffn_v   = (const float*)d_in[15];
    const float* ffn_wout= (const float*)d_in[16];
    const float* ffn_g   = (const float*)d_in[17];
    const float* rtf_wq  = (const float*)d_in[18];
    const float* rtf_wkv = (const float*)d_in[19];
    const float* rtf_wout= (const float*)d_in[20];
    float* out = (float*)d_out;

    float *pQ, *pKV, *pE, *pDn, *pAGG, *pX1, *pX2, *pT, *pH, *pV;
    cudaGetSymbolAddress((void**)&pQ, g_Q);
    cudaGetSymbolAddress((void**)&pKV, g_KV);
    cudaGetSymbolAddress((void**)&pE, g_E);
    cudaGetSymbolAddress((void**)&pDn, g_Dn);
    cudaGetSymbolAddress((void**)&pAGG, g_AGG);
    cudaGetSymbolAddress((void**)&pX1, g_X1);
    cudaGetSymbolAddress((void**)&pX2, g_X2);
    cudaGetSymbolAddress((void**)&pT, g_T);
    cudaGetSymbolAddress((void**)&pH, g_H);
    cudaGetSymbolAddress((void**)&pV, g_V);

    const float scale = 0.17677669529663687f;  // 1/sqrt(32)
    dim3 blk(256);
    dim3 egrid(E_EDGES / 8);
    dim3 ggrid256((256 + BN - 1) / BN, N_NODES / BM);
    dim3 ggrid512((512 + BN - 1) / BN, N_NODES / BM);
    dim3 ggrid768((768 + BN - 1) / BN, N_NODES / BM);
    dim3 ggridI((INTERM + BN - 1) / BN, N_NODES / BM);

    // ===== Stage 1: nodes_to_root CrossMHA =====
    gemm_k<<<ggrid256, blk>>>(root, ntr_wq, pQ, N_NODES, DIM, DIM);
    gemm_k<<<ggrid512, blk>>>(node, ntr_wkv, pKV, N_NODES, DIM, 512);
    cudaMemsetAsync(pDn, 0, (size_t)N_NODES * HEADS * 4, 0);
    cudaMemsetAsync(pAGG, 0, (size_t)N_NODES * DIM * 4, 0);
    edge_exp_cross<<<egrid, blk>>>(pQ, pKV, e_ntr, pE, pDn, scale);
    edge_agg_cross<<<egrid, blk>>>(pKV, e_ntr, pE, pDn, pAGG);
    gemm_k<<<ggrid256, blk>>>(pAGG, ntr_wout, pT, N_NODES, DIM, DIM);
    add_rms<<<N_NODES, blk>>>(root, pT, ntr_g, pX1);

    // ===== Stage 2: roots_to_root SelfMHA =====
    gemm_k<<<ggrid768, blk>>>(pX1, rtr_wqkv, pQ, N_NODES, DIM, 768);
    cudaMemsetAsync(pDn, 0, (size_t)N_NODES * HEADS * 4, 0);
    cudaMemsetAsync(pAGG, 0, (size_t)N_NODES * DIM * 4, 0);
    edge_exp_self<<<egrid, blk>>>(pQ, eattr, e_rtr, pE, pDn);
    edge_agg_self<<<egrid, blk>>>(pQ, e_rtr, pE, pDn, pAGG);
    gemm_k<<<ggrid256, blk>>>(pAGG, rtr_wout, pT, N_NODES, DIM, DIM);
    add_rms<<<N_NODES, blk>>>(pX1, pT, rtr_g, pX2);

    // ===== Stage 3: SwiGLU FFN (on root_features) =====
    gemm_k<<<ggridI, blk>>>(root, ffn_win, pH, N_NODES, DIM, INTERM);
    gemm_k<<<ggridI, blk>>>(root, ffn_v, pV, N_NODES, DIM, INTERM);
    {
        int total = N_NODES * INTERM;
        swiglu_k<<<(total + 255) / 256, blk>>>(pH, pV, total);
    }
    gemm_k<<<ggrid256, blk>>>(pH, ffn_wout, pT, N_NODES, INTERM, DIM);
    add_rms<<<N_NODES, blk>>>(pT, pX2, ffn_g, out);  // first output: ffn

    // ===== Stage 4: root_to_fringe CrossMHA (on original root/fringe feats) =====
    gemm_k<<<ggrid256, blk>>>(fringe, rtf_wq, pQ, N_NODES, DIM, DIM);
    gemm_k<<<ggrid512, blk>>>(root, rtf_wkv, pKV, N_NODES, DIM, 512);
    cudaMemsetAsync(pDn, 0, (size_t)N_NODES * HEADS * 4, 0);
    cudaMemsetAsync(pAGG, 0, (size_t)N_NODES * DIM * 4, 0);
    edge_exp_cross<<<egrid, blk>>>(pQ, pKV, e_rtf, pE, pDn, scale);
    edge_agg_cross<<<egrid, blk>>>(pKV, e_rtf, pE, pDn, pAGG);
    gemm_k<<<ggrid256, blk>>>(pAGG, rtf_wout, out + (size_t)N_NODES * DIM,
                              N_NODES, DIM, DIM);  // second output: fringe
}

// round 4
// speedup vs baseline: 1.7479x; 1.7479x over previous
#include <cuda_runtime.h>
#include <cuda_bf16.h>
#include <math.h>
#include <stdint.h>

#define N_NODES 16384
#define E_EDGES 131072
#define DIM 256
#define HEADS 8
#define HD_ 32
#define INTERM 682
#define INTERM_PAD 768

// ================= fp32 scratch =================
__device__ float g_Q[N_NODES * 768];
__device__ float g_KV[N_NODES * 512];
__device__ float g_E[E_EDGES * HEADS];
__device__ float g_Dn[N_NODES * HEADS];
__device__ float g_AGG[N_NODES * DIM];
__device__ float g_X1[N_NODES * DIM];
__device__ float g_X2[N_NODES * DIM];
__device__ float g_T[N_NODES * DIM];
__device__ float g_H[N_NODES * INTERM];
__device__ float g_V[N_NODES * INTERM];

// ================= bf16 hi/lo scratch (16B aligned for cp.async) =================
__device__ __align__(16) __nv_bfloat16 g_rootH[N_NODES * DIM], g_rootL[N_NODES * DIM];
__device__ __align__(16) __nv_bfloat16 g_nodeH[N_NODES * DIM], g_nodeL[N_NODES * DIM];
__device__ __align__(16) __nv_bfloat16 g_x1H[N_NODES * DIM],   g_x1L[N_NODES * DIM];
__device__ __align__(16) __nv_bfloat16 g_aggH[N_NODES * DIM],  g_aggL[N_NODES * DIM];
__device__ __align__(16) __nv_bfloat16 g_frH[N_NODES * DIM],   g_frL[N_NODES * DIM];
__device__ __align__(16) __nv_bfloat16 g_hH[N_NODES * INTERM_PAD], g_hL[N_NODES * INTERM_PAD];

// weight arena (transposed [Npad, Kpad], hi/lo)
#define OFF_WQ1   0
#define OFF_WKV1  65536
#define OFF_WOUT1 196608
#define OFF_WQKV  262144
#define OFF_WOUT2 458752
#define OFF_WIN   524288
#define OFF_WV    720896
#define OFF_WOUT3 917504
#define OFF_WQ4   1114112
#define OFF_WKV4  1179648
#define OFF_WOUT4 1310720
#define W_ARENA   1376256
__device__ __align__(16) __nv_bfloat16 g_wH[W_ARENA], g_wL[W_ARENA];

__device__ __forceinline__ uint32_t smem_u32(const void* p) {
    uint32_t a;
    asm("{ .reg .u64 t; cvta.to.shared.u64 t, %1; cvt.u32.u64 %0, t; }" : "=r"(a) : "l"(p));
    return a;
}

// ================= mma.sync bf16 split-precision GEMM =================
// C[M,Nc] = (Ah+Al)[M,K] @ (Bh+Bl)[Nc,K]^T , fp32 accum, 3 passes:
//   pass0: Ah*Bh   pass1: Al*Bh   pass2: Ah*Bl
// CTA tile 128x128, BK=32, 8 warps (4 in M x 2 in N), warp tile 32x64.
// SMEM rows have 80B stride (64B data + 16B pad) -> conflict-free STS/ldmatrix.
__global__ __launch_bounds__(256) void gemm_mma(
    const __nv_bfloat16* __restrict__ Ah, const __nv_bfloat16* __restrict__ Al,
    const __nv_bfloat16* __restrict__ Bh, const __nv_bfloat16* __restrict__ Bl,
    float* __restrict__ C, int Kpad, int Nc, int ldc) {
    __shared__ __align__(16) unsigned char sA[2][128 * 80];
    __shared__ __align__(16) unsigned char sB[2][128 * 80];

    int tid = threadIdx.x, lane = tid & 31, wid = tid >> 5;
    int wm = (wid & 3) << 5;   // warp row offset (0,32,64,96)
    int wn = (wid >> 2) << 6;  // warp col offset (0,64)
    int bm = blockIdx.y << 7, bn = blockIdx.x << 7;
    int kch = Kpad >> 5;       // K-chunks per pass
    int Q = kch * 3;

    float acc[2][8][4];
#pragma unroll
    for (int mi = 0; mi < 2; mi++)
#pragma unroll
        for (int ni = 0; ni < 8; ni++)
#pragma unroll
            for (int r = 0; r < 4; r++) acc[mi][ni][r] = 0.f;

    auto issue = [&](int q, int buf) {
        int p = q / kch;
        int kc = (q - p * kch) << 5;
        const __nv_bfloat16* Ap = (p == 1) ? Al : Ah;
        const __nv_bfloat16* Bp = (p == 2) ? Bl : Bh;
#pragma unroll
        for (int i = 0; i < 2; i++) {
            int cid = i * 256 + tid;
            int r = (cid & 7) + ((cid >> 5) << 3);
            int c = (cid >> 3) & 3;
            uint32_t off = (uint32_t)(r * 80 + c * 16);
            const char* ga = (const char*)Ap + ((size_t)(bm + r) * Kpad + kc) * 2 + c * 16;
            const char* gb = (const char*)Bp + ((size_t)(bn + r) * Kpad + kc) * 2 + c * 16;
            uint32_t sa = smem_u32(&sA[buf][0]) + off;
            uint32_t sb2 = smem_u32(&sB[buf][0]) + off;
            asm volatile("cp.async.cg.shared.global [%0], [%1], 16;" :: "r"(sa), "l"(ga));
            asm volatile("cp.async.cg.shared.global [%0], [%1], 16;" :: "r"(sb2), "l"(gb));
        }
        asm volatile("cp.async.commit_group;" ::: "memory");
    };

    issue(0, 0);
    for (int q = 0; q < Q; q++) {
        int buf = q & 1;
        if (q + 1 < Q) {
            issue(q + 1, buf ^ 1);
            asm volatile("cp.async.wait_group 1;" ::: "memory");
        } else {
            asm volatile("cp.async.wait_group 0;" ::: "memory");
        }
        __syncthreads();

#pragma unroll
        for (int ks = 0; ks < 2; ks++) {
            uint32_t a[2][4], b[8][2];
#pragma unroll
            for (int mi = 0; mi < 2; mi++) {
                uint32_t addr = smem_u32(&sA[buf][0]) +
                    (uint32_t)((wm + mi * 16 + (lane & 15)) * 80 + ks * 32 + ((lane >> 4) << 4));
                asm volatile("ldmatrix.sync.aligned.m8n8.x4.shared.b16 {%0,%1,%2,%3}, [%4];"
                             : "=r"(a[mi][0]), "=r"(a[mi][1]), "=r"(a[mi][2]), "=r"(a[mi][3])
                             : "r"(addr));
            }
#pragma unroll
            for (int nj = 0; nj < 4; nj++) {
                uint32_t addr = smem_u32(&sB[buf][0]) +
                    (uint32_t)((wn + nj * 16 + ((lane >> 4) << 3) + (lane & 7)) * 80 +
                               ks * 32 + (((lane >> 3) & 1) << 4));
                uint32_t d0, d1, d2, d3;
                asm volatile("ldmatrix.sync.aligned.m8n8.x4.shared.b16 {%0,%1,%2,%3}, [%4];"
                             : "=r"(d0), "=r"(d1), "=r"(d2), "=r"(d3) : "r"(addr));
                b[nj * 2][0] = d0;     b[nj * 2][1] = d1;
                b[nj * 2 + 1][0] = d2; b[nj * 2 + 1][1] = d3;
            }
#pragma unroll
            for (int mi = 0; mi < 2; mi++)
#pragma unroll
                for (int ni = 0; ni < 8; ni++) {
                    asm volatile(
                        "mma.sync.aligned.m16n8k16.row.col.f32.bf16.bf16.f32 "
                        "{%0,%1,%2,%3}, {%4,%5,%6,%7}, {%8,%9}, {%0,%1,%2,%3};"
                        : "+f"(acc[mi][ni][0]), "+f"(acc[mi][ni][1]),
                          "+f"(acc[mi][ni][2]), "+f"(acc[mi][ni][3])
                        : "r"(a[mi][0]), "r"(a[mi][1]), "r"(a[mi][2]), "r"(a[mi][3]),
                          "r"(b[ni][0]), "r"(b[ni][1]));
                }
        }
        __syncthreads();
    }

    // epilogue
#pragma unroll
    for (int mi = 0; mi < 2; mi++) {
#pragma unroll
        for (int ni = 0; ni < 8; ni++) {
            int row = bm + wm + mi * 16 + (lane >> 2);
            int col = bn + wn + ni * 8 + (lane & 3) * 2;
            if (col < Nc) {
                C[(size_t)row * ldc + col] = acc[mi][ni][0];
                C[(size_t)(row + 8) * ldc + col] = acc[mi][ni][2];
            }
            if (col + 1 < Nc) {
                C[(size_t)row * ldc + col + 1] = acc[mi][ni][1];
                C[(size_t)(row + 8) * ldc + col + 1] = acc[mi][ni][3];
            }
        }
    }
}

// ================= conversion kernels =================
__global__ void cvt_hilo(const float* __restrict__ src, __nv_bfloat16* __restrict__ hi,
                         __nv_bfloat16* __restrict__ lo, int M, int K, int Kpad) {
    int i = blockIdx.x * blockDim.x + threadIdx.x;
    if (i >= M * Kpad) return;
    int r = i / Kpad, c = i - r * Kpad;
    float x = (c < K) ? src[(size_t)r * K + c] : 0.f;
    __nv_bfloat16 h = __float2bfloat16(x);
    hi[i] = h;
    lo[i] = __float2bfloat16(x - __bfloat162float(h));
}

__global__ void cvt_w(const float* __restrict__ W, __nv_bfloat16* __restrict__ hi,
                      __nv_bfloat16* __restrict__ lo, int K, int N, int Kpad, int Npad) {
    int i = blockIdx.x * blockDim.x + threadIdx.x;
    if (i >= Npad * Kpad) return;
    int n = i / Kpad, k = i - n * Kpad;
    float x = (n < N && k < K) ? W[(size_t)k * N + n] : 0.f;
    __nv_bfloat16 h = __float2bfloat16(x);
    hi[i] = h;
    lo[i] = __float2bfloat16(x - __bfloat162float(h));
}

// ================= edge kernels (fp32) =================
__global__ void edge_exp_cross(const float* __restrict__ Q, const float* __restrict__ KV,
                               const int* __restrict__ eidx, float* __restrict__ ew,
                               float* __restrict__ den, float scale) {
    int e = blockIdx.x * 8 + (threadIdx.x >> 5);
    if (e >= E_EDGES) return;
    int lane = threadIdx.x & 31;
    int s = eidx[e];
    int d = eidx[E_EDGES + e];
    const float* qr = Q + (size_t)d * DIM;
    const float* kr = KV + (size_t)s * 512;
#pragma unroll
    for (int h = 0; h < HEADS; h++) {
        float p = qr[h * HD_ + lane] * kr[h * 64 + 2 * lane];
#pragma unroll
        for (int off = 16; off; off >>= 1) p += __shfl_xor_sync(0xffffffffu, p, off);
        float w = expf(p * scale);
        if (lane == 0) {
            ew[(size_t)e * HEADS + h] = w;
            atomicAdd(&den[(size_t)d * HEADS + h], w);
        }
    }
}

__global__ void edge_agg_cross(const float* __restrict__ KV, const int* __restrict__ eidx,
                               const float* __restrict__ ew, const float* __restrict__ den,
                               float* __restrict__ agg) {
    int e = blockIdx.x * 8 + (threadIdx.x >> 5);
    if (e >= E_EDGES) return;
    int lane = threadIdx.x & 31;
    int s = eidx[e];
    int d = eidx[E_EDGES + e];
    const float* kr = KV + (size_t)s * 512;
    float* ar = agg + (size_t)d * DIM;
#pragma unroll
    for (int h = 0; h < HEADS; h++) {
        float w = ew[(size_t)e * HEADS + h] / den[(size_t)d * HEADS + h];
        float v = kr[h * 64 + 2 * lane + 1];
        atomicAdd(&ar[h * HD_ + lane], w * v);
    }
}

__global__ void edge_exp_self(const float* __restrict__ QKV, const float* __restrict__ EA,
                              const int* __restrict__ eidx, float* __restrict__ ew,
                              float* __restrict__ den) {
    int e = blockIdx.x * 8 + (threadIdx.x >> 5);
    if (e >= E_EDGES) return;
    int lane = threadIdx.x & 31;
    int s = eidx[e];
    int d = eidx[E_EDGES + e];
    const float* qr = QKV + (size_t)d * 768;
    const float* kr = QKV + (size_t)s * 768;
    const float* ar = EA + (size_t)e * DIM;
#pragma unroll
    for (int h = 0; h < HEADS; h++) {
        float p = qr[h * 96 + 3 * lane] * kr[h * 96 + 3 * lane + 1] * ar[h * HD_ + lane];
#pragma unroll
        for (int off = 16; off; off >>= 1) p += __shfl_xor_sync(0xffffffffu, p, off);
        float w = expf(p);
        if (lane == 0) {
            ew[(size_t)e * HEADS + h] = w;
            atomicAdd(&den[(size_t)d * HEADS + h], w);
        }
    }
}

__global__ void edge_agg_self(const float* __restrict__ QKV, const int* __restrict__ eidx,
                              const float* __restrict__ ew, const float* __restrict__ den,
                              float* __restrict__ agg) {
    int e = blockIdx.x * 8 + (threadIdx.x >> 5);
    if (e >= E_EDGES) return;
    int lane = threadIdx.x & 31;
    int s = eidx[e];
    int d = eidx[E_EDGES + e];
    const float* kr = QKV + (size_t)s * 768;
    float* ar = agg + (size_t)d * DIM;
#pragma unroll
    for (int h = 0; h < HEADS; h++) {
        float w = ew[(size_t)e * HEADS + h] / den[(size_t)d * HEADS + h];
        float v = kr[h * 96 + 3 * lane + 2];
        atomicAdd(&ar[h * HD_ + lane], w * v);
    }
}

// ================= add + RMS norm =================
__global__ void add_rms(const float* __restrict__ A, const float* __restrict__ B,
                        const float* __restrict__ g, float* __restrict__ out) {
    int row = blockIdx.x;
    int t = threadIdx.x;
    float x = A[(size_t)row * DIM + t] + B[(size_t)row * DIM + t];
    float ss = x * x;
#pragma unroll
    for (int off = 16; off; off >>= 1) ss += __shfl_xor_sync(0xffffffffu, ss, off);
    __shared__ float sh[8];
    if ((t & 31) == 0) sh[t >> 5] = ss;
    __syncthreads();
    float tot = sh[0] + sh[1] + sh[2] + sh[3] + sh[4] + sh[5] + sh[6] + sh[7];
    float nrm = sqrtf(tot * (1.0f / DIM));
    out[(size_t)row * DIM + t] = x / fmaxf(nrm, 1e-8f) * g[t];
}

__global__ void swiglu_k(float* __restrict__ H, const float* __restrict__ V, int total) {
    int i = blockIdx.x * blockDim.x + threadIdx.x;
    if (i < total) {
        float h = H[i];
        H[i] = h / (1.0f + expf(-h)) * V[i];
    }
}

// ================= launch =================
extern "C" void kernel_launch(void* const* d_in, const int* in_sizes, int n_in,
                              void* d_out, int out_size) {
    const float* root   = (const float*)d_in[0];
    const float* node   = (const float*)d_in[1];
    const float* fringe = (const float*)d_in[2];
    const int* e_ntr = (const int*)d_in[3];
    const int* e_rtr = (const int*)d_in[4];
    const int* e_rtf = (const int*)d_in[5];
    const float* eattr = (const float*)d_in[6];
    const float* ntr_wq  = (const float*)d_in[7];
    const float* ntr_wkv = (const float*)d_in[8];
    const float* ntr_wout= (const float*)d_in[9];
    const float* ntr_g   = (const float*)d_in[10];
    const float* rtr_wqkv= (const float*)d_in[11];
    const float* rtr_wout= (const float*)d_in[12];
    const float* rtr_g   = (const float*)d_in[13];
    const float* ffn_win = (const float*)d_in[14];
    const float* ffn_v   = (const float*)d_in[15];
    const float* ffn_wout= (const float*)d_in[16];
    const float* ffn_g   = (const float*)d_in[17];
    const float* rtf_wq  = (const float*)d_in[18];
    const float* rtf_wkv = (const float*)d_in[19];
    const float* rtf_wout= (const float*)d_in[20];
    float* out = (float*)d_out;

    float *pQ, *pKV, *pE, *pDn, *pAGG, *pX1, *pX2, *pT, *pH, *pV;
    cudaGetSymbolAddress((void**)&pQ, g_Q);
    cudaGetSymbolAddress((void**)&pKV, g_KV);
    cudaGetSymbolAddress((void**)&pE, g_E);
    cudaGetSymbolAddress((void**)&pDn, g_Dn);
    cudaGetSymbolAddress((void**)&pAGG, g_AGG);
    cudaGetSymbolAddress((void**)&pX1, g_X1);
    cudaGetSymbolAddress((void**)&pX2, g_X2);
    cudaGetSymbolAddress((void**)&pT, g_T);
    cudaGetSymbolAddress((void**)&pH, g_H);
    cudaGetSymbolAddress((void**)&pV, g_V);

    __nv_bfloat16 *rH, *rL, *nH, *nL, *x1H, *x1L, *aH, *aL, *fH, *fL, *hH, *hL, *wH, *wL;
    cudaGetSymbolAddress((void**)&rH, g_rootH);  cudaGetSymbolAddress((void**)&rL, g_rootL);
    cudaGetSymbolAddress((void**)&nH, g_nodeH);  cudaGetSymbolAddress((void**)&nL, g_nodeL);
    cudaGetSymbolAddress((void**)&x1H, g_x1H);   cudaGetSymbolAddress((void**)&x1L, g_x1L);
    cudaGetSymbolAddress((void**)&aH, g_aggH);   cudaGetSymbolAddress((void**)&aL, g_aggL);
    cudaGetSymbolAddress((void**)&fH, g_frH);    cudaGetSymbolAddress((void**)&fL, g_frL);
    cudaGetSymbolAddress((void**)&hH, g_hH);     cudaGetSymbolAddress((void**)&hL, g_hL);
    cudaGetSymbolAddress((void**)&wH, g_wH);     cudaGetSymbolAddress((void**)&wL, g_wL);

    const float scale = 0.17677669529663687f;  // 1/sqrt(32)
    dim3 blk(256);
    dim3 egrid(E_EDGES / 8);
    const int CVT = 256;

    auto nblk = [](int total) { return (total + 255) / 256; };

#define GEMM(AHi, ALo, woff, Cptr, Kpad, Nc, ldc, ntiles) \
    gemm_mma<<<dim3(ntiles, 128), 256>>>(AHi, ALo, wH + (woff), wL + (woff), Cptr, Kpad, Nc, ldc)

    // ---- input conversions ----
    cvt_hilo<<<nblk(N_NODES * DIM), CVT>>>(root, rH, rL, N_NODES, DIM, DIM);
    cvt_hilo<<<nblk(N_NODES * DIM), CVT>>>(node, nH, nL, N_NODES, DIM, DIM);
    cvt_hilo<<<nblk(N_NODES * DIM), CVT>>>(fringe, fH, fL, N_NODES, DIM, DIM);
    cvt_w<<<nblk(256 * 256), CVT>>>(ntr_wq, wH + OFF_WQ1, wL + OFF_WQ1, 256, 256, 256, 256);
    cvt_w<<<nblk(512 * 256), CVT>>>(ntr_wkv, wH + OFF_WKV1, wL + OFF_WKV1, 256, 512, 256, 512);
    cvt_w<<<nblk(256 * 256), CVT>>>(ntr_wout, wH + OFF_WOUT1, wL + OFF_WOUT1, 256, 256, 256, 256);
    cvt_w<<<nblk(768 * 256), CVT>>>(rtr_wqkv, wH + OFF_WQKV, wL + OFF_WQKV, 256, 768, 256, 768);
    cvt_w<<<nblk(256 * 256), CVT>>>(rtr_wout, wH + OFF_WOUT2, wL + OFF_WOUT2, 256, 256, 256, 256);
    cvt_w<<<nblk(768 * 256), CVT>>>(ffn_win, wH + OFF_WIN, wL + OFF_WIN, 256, INTERM, 256, 768);
    cvt_w<<<nblk(768 * 256), CVT>>>(ffn_v, wH + OFF_WV, wL + OFF_WV, 256, INTERM, 256, 768);
    cvt_w<<<nblk(256 * 768), CVT>>>(ffn_wout, wH + OFF_WOUT3, wL + OFF_WOUT3, INTERM, 256, 768, 256);
    cvt_w<<<nblk(256 * 256), CVT>>>(rtf_wq, wH + OFF_WQ4, wL + OFF_WQ4, 256, 256, 256, 256);
    cvt_w<<<nblk(512 * 256), CVT>>>(rtf_wkv, wH + OFF_WKV4, wL + OFF_WKV4, 256, 512, 256, 512);
    cvt_w<<<nblk(256 * 256), CVT>>>(rtf_wout, wH + OFF_WOUT4, wL + OFF_WOUT4, 256, 256, 256, 256);

    // ===== Stage 1: nodes_to_root CrossMHA =====
    GEMM(rH, rL, OFF_WQ1, pQ, 256, 256, 256, 2);
    GEMM(nH, nL, OFF_WKV1, pKV, 256, 512, 512, 4);
    cudaMemsetAsync(pDn, 0, (size_t)N_NODES * HEADS * 4, 0);
    cudaMemsetAsync(pAGG, 0, (size_t)N_NODES * DIM * 4, 0);
    edge_exp_cross<<<egrid, blk>>>(pQ, pKV, e_ntr, pE, pDn, scale);
    edge_agg_cross<<<egrid, blk>>>(pKV, e_ntr, pE, pDn, pAGG);
    cvt_hilo<<<nblk(N_NODES * DIM), CVT>>>(pAGG, aH, aL, N_NODES, DIM, DIM);
    GEMM(aH, aL, OFF_WOUT1, pT, 256, 256, 256, 2);
    add_rms<<<N_NODES, blk>>>(root, pT, ntr_g, pX1);

    // ===== Stage 2: roots_to_root SelfMHA =====
    cvt_hilo<<<nblk(N_NODES * DIM), CVT>>>(pX1, x1H, x1L, N_NODES, DIM, DIM);
    GEMM(x1H, x1L, OFF_WQKV, pQ, 256, 768, 768, 6);
    cudaMemsetAsync(pDn, 0, (size_t)N_NODES * HEADS * 4, 0);
    cudaMemsetAsync(pAGG, 0, (size_t)N_NODES * DIM * 4, 0);
    edge_exp_self<<<egrid, blk>>>(pQ, eattr, e_rtr, pE, pDn);
    edge_agg_self<<<egrid, blk>>>(pQ, e_rtr, pE, pDn, pAGG);
    cvt_hilo<<<nblk(N_NODES * DIM), CVT>>>(pAGG, aH, aL, N_NODES, DIM, DIM);
    GEMM(aH, aL, OFF_WOUT2, pT, 256, 256, 256, 2);
    add_rms<<<N_NODES, blk>>>(pX1, pT, rtr_g, pX2);

    // ===== Stage 3: SwiGLU FFN (on root_features) =====
    GEMM(rH, rL, OFF_WIN, pH, 256, INTERM, INTERM, 6);
    GEMM(rH, rL, OFF_WV, pV, 256, INTERM, INTERM, 6);
    {
        int total = N_NODES * INTERM;
        swiglu_k<<<nblk(total), blk>>>(pH, pV, total);
    }
    cvt_hilo<<<nblk(N_NODES * INTERM_PAD), CVT>>>(pH, hH, hL, N_NODES, INTERM, INTERM_PAD);
    GEMM(hH, hL, OFF_WOUT3, pT, INTERM_PAD, 256, 256, 2);
    add_rms<<<N_NODES, blk>>>(pT, pX2, ffn_g, out);  // output 0: ffn

    // ===== Stage 4: root_to_fringe CrossMHA =====
    GEMM(fH, fL, OFF_WQ4, pQ, 256, 256, 256, 2);
    GEMM(rH, rL, OFF_WKV4, pKV, 256, 512, 512, 4);
    cudaMemsetAsync(pDn, 0, (size_t)N_NODES * HEADS * 4, 0);
    cudaMemsetAsync(pAGG, 0, (size_t)N_NODES * DIM * 4, 0);
    edge_exp_cross<<<egrid, blk>>>(pQ, pKV, e_rtf, pE, pDn, scale);
    edge_agg_cross<<<egrid, blk>>>(pKV, e_rtf, pE, pDn, pAGG);
    cvt_hilo<<<nblk(N_NODES * DIM), CVT>>>(pAGG, aH, aL, N_NODES, DIM, DIM);
    GEMM(aH, aL, OFF_WOUT4, out + (size_t)N_NODES * DIM, 256, 256, 256, 2);  // output 1: fringe
#undef GEMM
}